// round 3
// baseline (speedup 1.0000x reference)
#include <cuda_runtime.h>

#define B_SZ   65536
#define IN_SZ  512
#define HID_SZ 512
#define FAN    1024
#define NZ     32          // NGATES * NQ
#define THREADS 512
#define NBLK   (B_SZ / THREADS)   // 128

typedef unsigned long long u64;

// Pre-transposed weights (filled by prep_kernel each launch; deterministic).
__device__ float g_W1t[FAN * NZ];          // [k][gq]     gq = g*8+q
__device__ float g_W2t[4 * 8 * HID_SZ];    // [g][q][h]

__device__ __forceinline__ u64 pk2(float a, float b) {
    u64 r; asm("mov.b64 %0, {%1,%2};" : "=l"(r) : "f"(a), "f"(b)); return r;
}
__device__ __forceinline__ void upk2(u64 v, float& a, float& b) {
    asm("mov.b64 {%0,%1}, %2;" : "=f"(a), "=f"(b) : "l"(v));
}
// packed dual-FMA on Blackwell fp32 pipe: d = a*b + d (two lanes)
__device__ __forceinline__ void ffma2(u64& d, u64 a, u64 b) {
    asm("fma.rn.f32x2 %0, %1, %2, %0;" : "+l"(d) : "l"(a), "l"(b));
}
__device__ __forceinline__ float sigm(float xv) {
    return __fdividef(1.0f, 1.0f + __expf(-xv));
}
__device__ __forceinline__ float tanh_acc(float xv) {
    return 2.0f * sigm(2.0f * xv) - 1.0f;
}

__global__ void prep_kernel(const float* __restrict__ W1, const float* __restrict__ W2) {
    int t = blockIdx.x * blockDim.x + threadIdx.x;
    if (t < FAN * NZ) {
        // W1 is [4][8][1024] -> W1t[k][gq]
        int k = t >> 5, gq = t & 31;
        g_W1t[t] = W1[gq * FAN + k];
    } else {
        int t2 = t - FAN * NZ;
        if (t2 < 4 * 8 * HID_SZ) {
            // W2 is [4][512][8] -> W2t[g][q][h]
            int g = t2 >> 12, rem = t2 & 4095, q = rem >> 9, hh = rem & 511;
            g_W2t[t2] = W2[g * 4096 + hh * 8 + q];
        }
    }
}

__global__ __launch_bounds__(THREADS, 1)
void lstm_kernel(const float* __restrict__ x, const float* __restrict__ h,
                 const float* __restrict__ c, const float* __restrict__ b1,
                 const float* __restrict__ b2, float* __restrict__ out) {
    extern __shared__ float smem[];
    float* W1s = smem;               // 32768 floats  (128 KB)  [k][32]
    float* W2s = smem + 32768;       // 16384 floats  ( 64 KB)  [g][q][512]
    float* b2s = smem + 49152;       //  2048 floats  (  8 KB)  [g][512]
    float* b1s = smem + 51200;       //    32 floats

    const int tid = threadIdx.x;
    {   // cooperative smem fill (coalesced, conflict-free)
        float4* d1 = (float4*)W1s; const float4* s1 = (const float4*)g_W1t;
        for (int i = tid; i < 8192; i += THREADS) d1[i] = s1[i];
        float4* d2 = (float4*)W2s; const float4* s2 = (const float4*)g_W2t;
        for (int i = tid; i < 4096; i += THREADS) d2[i] = s2[i];
        float4* d3 = (float4*)b2s; const float4* s3 = (const float4*)b2;
        for (int i = tid; i < 512; i += THREADS) d3[i] = s3[i];
        if (tid < 32) b1s[tid] = b1[tid];
    }
    __syncthreads();

    const int row = blockIdx.x * THREADS + tid;
    const float* xr = x + (size_t)row * IN_SZ;
    const float* hr = h + (size_t)row * HID_SZ;

    // ---------------- GEMM1: z_pre[32] = combined[1024] . W1t ----------------
    // acc[p] holds fp32x2 pair (gq=2p, gq=2p+1)
    u64 acc[16];
    #pragma unroll
    for (int p = 0; p < 16; p++) acc[p] = 0ULL;

    float4 v = *(const float4*)xr;
    #pragma unroll 1
    for (int k0 = 0; k0 < FAN; k0 += 4) {
        const int kn = k0 + 4;
        float4 vn = v;
        if (kn < FAN)
            vn = *(const float4*)((kn < IN_SZ) ? (xr + kn) : (hr + (kn - IN_SZ)));
        float cv[4] = {v.x, v.y, v.z, v.w};
        #pragma unroll
        for (int kk = 0; kk < 4; kk++) {
            u64 a2 = pk2(cv[kk], cv[kk]);
            const ulonglong2* wr = (const ulonglong2*)(W1s + (k0 + kk) * NZ);
            #pragma unroll
            for (int p = 0; p < 8; p++) {
                ulonglong2 w = wr[p];          // LDS.128: 4 W1 values (2 pairs), broadcast
                ffma2(acc[2*p],     a2, w.x);
                ffma2(acc[2*p + 1], a2, w.y);
            }
        }
        v = vn;
    }

    // z = tanh(z_pre + b1); duplicate-pack each z into both f32x2 lanes
    u64 z2[32];
    #pragma unroll
    for (int p = 0; p < 16; p++) {
        float a, b; upk2(acc[p], a, b);
        a = tanh_acc(a + b1s[2*p]);
        b = tanh_acc(b + b1s[2*p + 1]);
        z2[2*p]     = pk2(a, a);
        z2[2*p + 1] = pk2(b, b);
    }

    // ---------------- GEMM2 + gating epilogue, 4 h-outputs per iteration ----------------
    const float* cr  = c   + (size_t)row * HID_SZ;
    float* hnr = out + (size_t)row * HID_SZ;
    float* cnr = out + (size_t)B_SZ * HID_SZ + (size_t)row * HID_SZ;

    #pragma unroll 1
    for (int h0 = 0; h0 < HID_SZ; h0 += 4) {
        float pre[4][4];
        #pragma unroll
        for (int g = 0; g < 4; g++) {
            ulonglong2 bb = *(const ulonglong2*)(b2s + g * HID_SZ + h0);
            u64 a0 = bb.x, a1 = bb.y;        // pairs (h0,h0+1) and (h0+2,h0+3)
            const float* wg = W2s + g * (8 * HID_SZ) + h0;
            #pragma unroll
            for (int q = 0; q < 8; q++) {
                ulonglong2 w = *(const ulonglong2*)(wg + q * HID_SZ);
                ffma2(a0, z2[g*8 + q], w.x);
                ffma2(a1, z2[g*8 + q], w.y);
            }
            upk2(a0, pre[g][0], pre[g][1]);
            upk2(a1, pre[g][2], pre[g][3]);
        }
        float4 cvv = *(const float4*)(cr + h0);
        float ca[4] = {cvv.x, cvv.y, cvv.z, cvv.w};
        float hn[4], cn[4];
        #pragma unroll
        for (int j = 0; j < 4; j++) {
            float ig = sigm(pre[0][j]);
            float fg = sigm(pre[1][j]);
            float og = sigm(pre[2][j]);
            float gg = sigm(pre[3][j]);
            float cj = fg * ca[j] + ig * gg;
            cn[j] = cj;
            hn[j] = og * tanh_acc(cj);
        }
        *(float4*)(hnr + h0) = make_float4(hn[0], hn[1], hn[2], hn[3]);
        *(float4*)(cnr + h0) = make_float4(cn[0], cn[1], cn[2], cn[3]);
    }
}

extern "C" void kernel_launch(void* const* d_in, const int* in_sizes, int n_in,
                              void* d_out, int out_size) {
    const float* x  = (const float*)d_in[0];
    const float* h  = (const float*)d_in[1];
    const float* c  = (const float*)d_in[2];
    const float* W1 = (const float*)d_in[3];
    const float* b1 = (const float*)d_in[4];
    const float* W2 = (const float*)d_in[5];
    const float* b2 = (const float*)d_in[6];
    float* out = (float*)d_out;

    prep_kernel<<<192, 256>>>(W1, W2);   // 192*256 = 49152 = 32768 + 16384

    const size_t smem_bytes = (size_t)(32768 + 16384 + 2048 + 32) * sizeof(float); // 204,928 B
    cudaFuncSetAttribute(lstm_kernel, cudaFuncAttributeMaxDynamicSharedMemorySize,
                         (int)smem_bytes);
    lstm_kernel<<<NBLK, THREADS, smem_bytes>>>(x, h, c, b1, b2, out);
}

// round 4
// speedup vs baseline: 1.0033x; 1.0033x over previous
#include <cuda_runtime.h>

#define B_SZ   65536
#define IN_SZ  512
#define HID_SZ 512
#define FAN    1024
#define NZ     32          // NGATES * NQ
#define THREADS 512
#define NBLK   (B_SZ / THREADS)   // 128

typedef unsigned long long u64;

// Pre-transposed weights (filled by prep_kernel each launch; deterministic).
__device__ float g_W1t[FAN * NZ];          // [k][gq]     gq = g*8+q
__device__ float g_W2t[4 * 8 * HID_SZ];    // [g][q][h]

__device__ __forceinline__ u64 pk2(float a, float b) {
    u64 r; asm("mov.b64 %0, {%1,%2};" : "=l"(r) : "f"(a), "f"(b)); return r;
}
__device__ __forceinline__ void upk2(u64 v, float& a, float& b) {
    asm("mov.b64 {%0,%1}, %2;" : "=f"(a), "=f"(b) : "l"(v));
}
// packed dual-FMA on Blackwell fp32 pipe: d = a*b + d (two lanes)
__device__ __forceinline__ void ffma2(u64& d, u64 a, u64 b) {
    asm("fma.rn.f32x2 %0, %1, %2, %0;" : "+l"(d) : "l"(a), "l"(b));
}
__device__ __forceinline__ float sigm(float xv) {
    return __fdividef(1.0f, 1.0f + __expf(-xv));
}
__device__ __forceinline__ float tanh_acc(float xv) {
    return 2.0f * sigm(2.0f * xv) - 1.0f;
}

__global__ void prep_kernel(const float* __restrict__ W1, const float* __restrict__ W2) {
    int t = blockIdx.x * blockDim.x + threadIdx.x;
    if (t < FAN * NZ) {
        // W1 is [4][8][1024] -> W1t[k][gq]
        int k = t >> 5, gq = t & 31;
        g_W1t[t] = W1[gq * FAN + k];
    } else {
        int t2 = t - FAN * NZ;
        if (t2 < 4 * 8 * HID_SZ) {
            // W2 is [4][512][8] -> W2t[g][q][h]
            int g = t2 >> 12, rem = t2 & 4095, q = rem >> 9, hh = rem & 511;
            g_W2t[t2] = W2[g * 4096 + hh * 8 + q];
        }
    }
}

__global__ __launch_bounds__(THREADS, 1)
void lstm_kernel(const float* __restrict__ x, const float* __restrict__ h,
                 const float* __restrict__ c, const float* __restrict__ b1,
                 const float* __restrict__ b2, float* __restrict__ out) {
    extern __shared__ float smem[];
    float* W1s = smem;               // 32768 floats  (128 KB)  [k][32]
    float* W2s = smem + 32768;       // 16384 floats  ( 64 KB)  [g][q][512]
    float* b2s = smem + 49152;       //  2048 floats  (  8 KB)  [g][512]
    float* b1s = smem + 51200;       //    32 floats

    const int tid = threadIdx.x;
    {   // cooperative smem fill (coalesced, conflict-free)
        float4* d1 = (float4*)W1s; const float4* s1 = (const float4*)g_W1t;
        for (int i = tid; i < 8192; i += THREADS) d1[i] = s1[i];
        float4* d2 = (float4*)W2s; const float4* s2 = (const float4*)g_W2t;
        for (int i = tid; i < 4096; i += THREADS) d2[i] = s2[i];
        float4* d3 = (float4*)b2s; const float4* s3 = (const float4*)b2;
        for (int i = tid; i < 512; i += THREADS) d3[i] = s3[i];
        if (tid < 32) b1s[tid] = b1[tid];
    }
    __syncthreads();

    const int row = blockIdx.x * THREADS + tid;
    const float* xr = x + (size_t)row * IN_SZ;
    const float* hr = h + (size_t)row * HID_SZ;

    // ---------------- GEMM1: z_pre[32] = combined[1024] . W1t ----------------
    // acc[p] holds fp32x2 pair (gq=2p, gq=2p+1)
    u64 acc[16];
    #pragma unroll
    for (int p = 0; p < 16; p++) acc[p] = 0ULL;

    float4 v = *(const float4*)xr;
    #pragma unroll 1
    for (int k0 = 0; k0 < FAN; k0 += 4) {
        const int kn = k0 + 4;
        float4 vn = v;
        if (kn < FAN)
            vn = *(const float4*)((kn < IN_SZ) ? (xr + kn) : (hr + (kn - IN_SZ)));
        float cv[4] = {v.x, v.y, v.z, v.w};
        #pragma unroll
        for (int kk = 0; kk < 4; kk++) {
            u64 a2 = pk2(cv[kk], cv[kk]);
            const ulonglong2* wr = (const ulonglong2*)(W1s + (k0 + kk) * NZ);
            #pragma unroll
            for (int p = 0; p < 8; p++) {
                ulonglong2 w = wr[p];          // LDS.128: 4 W1 values (2 pairs), broadcast
                ffma2(acc[2*p],     a2, w.x);
                ffma2(acc[2*p + 1], a2, w.y);
            }
        }
        v = vn;
    }

    // z = tanh(z_pre + b1); duplicate-pack each z into both f32x2 lanes
    u64 z2[32];
    #pragma unroll
    for (int p = 0; p < 16; p++) {
        float a, b; upk2(acc[p], a, b);
        a = tanh_acc(a + b1s[2*p]);
        b = tanh_acc(b + b1s[2*p + 1]);
        z2[2*p]     = pk2(a, a);
        z2[2*p + 1] = pk2(b, b);
    }

    // ---------------- GEMM2 + gating epilogue, 4 h-outputs per iteration ----------------
    const float* cr  = c   + (size_t)row * HID_SZ;
    float* hnr = out + (size_t)row * HID_SZ;
    float* cnr = out + (size_t)B_SZ * HID_SZ + (size_t)row * HID_SZ;

    #pragma unroll 1
    for (int h0 = 0; h0 < HID_SZ; h0 += 4) {
        float pre[4][4];
        #pragma unroll
        for (int g = 0; g < 4; g++) {
            ulonglong2 bb = *(const ulonglong2*)(b2s + g * HID_SZ + h0);
            u64 a0 = bb.x, a1 = bb.y;        // pairs (h0,h0+1) and (h0+2,h0+3)
            const float* wg = W2s + g * (8 * HID_SZ) + h0;
            #pragma unroll
            for (int q = 0; q < 8; q++) {
                ulonglong2 w = *(const ulonglong2*)(wg + q * HID_SZ);
                ffma2(a0, z2[g*8 + q], w.x);
                ffma2(a1, z2[g*8 + q], w.y);
            }
            upk2(a0, pre[g][0], pre[g][1]);
            upk2(a1, pre[g][2], pre[g][3]);
        }
        float4 cvv = *(const float4*)(cr + h0);
        float ca[4] = {cvv.x, cvv.y, cvv.z, cvv.w};
        float hn[4], cn[4];
        #pragma unroll
        for (int j = 0; j < 4; j++) {
            float ig = sigm(pre[0][j]);
            float fg = sigm(pre[1][j]);
            float og = sigm(pre[2][j]);
            float gg = sigm(pre[3][j]);
            float cj = fg * ca[j] + ig * gg;
            cn[j] = cj;
            hn[j] = og * tanh_acc(cj);
        }
        *(float4*)(hnr + h0) = make_float4(hn[0], hn[1], hn[2], hn[3]);
        *(float4*)(cnr + h0) = make_float4(cn[0], cn[1], cn[2], cn[3]);
    }
}

extern "C" void kernel_launch(void* const* d_in, const int* in_sizes, int n_in,
                              void* d_out, int out_size) {
    const float* x  = (const float*)d_in[0];
    const float* h  = (const float*)d_in[1];
    const float* c  = (const float*)d_in[2];
    const float* W1 = (const float*)d_in[3];
    const float* b1 = (const float*)d_in[4];
    const float* W2 = (const float*)d_in[5];
    const float* b2 = (const float*)d_in[6];
    float* out = (float*)d_out;

    prep_kernel<<<192, 256>>>(W1, W2);   // 192*256 = 49152 = 32768 + 16384

    const size_t smem_bytes = (size_t)(32768 + 16384 + 2048 + 32) * sizeof(float); // 204,928 B
    cudaFuncSetAttribute(lstm_kernel, cudaFuncAttributeMaxDynamicSharedMemorySize,
                         (int)smem_bytes);
    lstm_kernel<<<NBLK, THREADS, smem_bytes>>>(x, h, c, b1, b2, out);
}

// round 5
// speedup vs baseline: 1.1652x; 1.1613x over previous
#include <cuda_runtime.h>

#define B_SZ   65536
#define IN_SZ  512
#define HID_SZ 512
#define FAN    1024
#define NZ     32          // NGATES * NQ
#define THREADS 256
#define ROWS_PER_CTA 512   // 256 threads x 2 rows
#define NBLK   (B_SZ / ROWS_PER_CTA)   // 128

typedef unsigned long long u64;

// Pre-transposed weights (filled by prep_kernel each launch; deterministic).
__device__ float g_W1t[FAN * NZ];          // [k][gq]     gq = g*8+q
__device__ float g_W2t[4 * 8 * HID_SZ];    // [g][q][h]

__device__ __forceinline__ u64 pk2(float a, float b) {
    u64 r; asm("mov.b64 %0, {%1,%2};" : "=l"(r) : "f"(a), "f"(b)); return r;
}
__device__ __forceinline__ void upk2(u64 v, float& a, float& b) {
    asm("mov.b64 {%0,%1}, %2;" : "=f"(a), "=f"(b) : "l"(v));
}
// packed dual-FMA on Blackwell fp32 pipe: d = a*b + d (two lanes)
__device__ __forceinline__ void ffma2(u64& d, u64 a, u64 b) {
    asm("fma.rn.f32x2 %0, %1, %2, %0;" : "+l"(d) : "l"(a), "l"(b));
}
// exact-ish tanh (used only for the 32 z values per row; error ~1e-7)
__device__ __forceinline__ float tanh_acc(float xv) {
    float s = __fdividef(1.0f, 1.0f + __expf(-2.0f * xv));
    return 2.0f * s - 1.0f;
}
// HW MUFU.TANH (1 MUFU op), rel err ~2^-11 — plenty for sigmoid gates
__device__ __forceinline__ float tanh_fast(float xv) {
    float y; asm("tanh.approx.f32 %0, %1;" : "=f"(y) : "f"(xv)); return y;
}
__device__ __forceinline__ float sigm_fast(float xv) {
    return fmaf(tanh_fast(0.5f * xv), 0.5f, 0.5f);
}

__global__ void prep_kernel(const float* __restrict__ W1, const float* __restrict__ W2) {
    int t = blockIdx.x * blockDim.x + threadIdx.x;
    if (t < FAN * NZ) {
        // W1 is [4][8][1024] -> W1t[k][gq]
        int k = t >> 5, gq = t & 31;
        g_W1t[t] = W1[gq * FAN + k];
    } else {
        int t2 = t - FAN * NZ;
        if (t2 < 4 * 8 * HID_SZ) {
            // W2 is [4][512][8] -> W2t[g][q][h]
            int g = t2 >> 12, rem = t2 & 4095, q = rem >> 9, hh = rem & 511;
            g_W2t[t2] = W2[g * 4096 + hh * 8 + q];
        }
    }
}

// Accumulate one 512-wide half of the fan-in for two rows.
// acc*(16 u64 each) hold fp32x2 pairs (gq=2p, gq=2p+1).
__device__ __forceinline__ void gemm1_half(const float* __restrict__ p0,
                                           const float* __restrict__ p1,
                                           const float* __restrict__ W1s,
                                           const float* __restrict__ Wbase,
                                           u64* acc0, u64* acc1) {
    float4 v0a = *(const float4*)(p0);
    float4 v0b = *(const float4*)(p0 + 4);
    float4 v1a = *(const float4*)(p1);
    float4 v1b = *(const float4*)(p1 + 4);
    #pragma unroll 1
    for (int k0 = 0; k0 < 512; k0 += 8) {
        const int kn = (k0 + 8 < 512) ? (k0 + 8) : k0;   // clamped prefetch
        float4 n0a = *(const float4*)(p0 + kn);
        float4 n0b = *(const float4*)(p0 + kn + 4);
        float4 n1a = *(const float4*)(p1 + kn);
        float4 n1b = *(const float4*)(p1 + kn + 4);

        float c0[8] = {v0a.x, v0a.y, v0a.z, v0a.w, v0b.x, v0b.y, v0b.z, v0b.w};
        float c1[8] = {v1a.x, v1a.y, v1a.z, v1a.w, v1b.x, v1b.y, v1b.z, v1b.w};
        #pragma unroll
        for (int kk = 0; kk < 8; kk++) {
            u64 a0 = pk2(c0[kk], c0[kk]);
            u64 a1 = pk2(c1[kk], c1[kk]);
            const ulonglong2* wr = (const ulonglong2*)(Wbase + (k0 + kk) * NZ);
            #pragma unroll
            for (int p = 0; p < 8; p++) {
                ulonglong2 w = wr[p];          // LDS.128 broadcast: 4 W1 vals
                ffma2(acc0[2*p],     a0, w.x);
                ffma2(acc0[2*p + 1], a0, w.y);
                ffma2(acc1[2*p],     a1, w.x);
                ffma2(acc1[2*p + 1], a1, w.y);
            }
        }
        v0a = n0a; v0b = n0b; v1a = n1a; v1b = n1b;
    }
    (void)W1s;
}

__global__ __launch_bounds__(THREADS, 1)
void lstm_kernel(const float* __restrict__ x, const float* __restrict__ h,
                 const float* __restrict__ c, const float* __restrict__ b1,
                 const float* __restrict__ b2, float* __restrict__ out) {
    extern __shared__ float smem[];
    float* W1s = smem;               // 32768 floats (128 KB)  [k][32]
    float* W2s = smem + 32768;       // 16384 floats ( 64 KB)  [g][q][512]
    float* b2s = smem + 49152;       //  2048 floats (  8 KB)  [g][512]
    float* b1s = smem + 51200;       //    32 floats

    const int tid = threadIdx.x;
    {   // cooperative smem fill (coalesced, conflict-free)
        float4* d1 = (float4*)W1s; const float4* s1 = (const float4*)g_W1t;
        #pragma unroll
        for (int i = 0; i < 32; i++) d1[tid + i * THREADS] = s1[tid + i * THREADS];
        float4* d2 = (float4*)W2s; const float4* s2 = (const float4*)g_W2t;
        #pragma unroll
        for (int i = 0; i < 16; i++) d2[tid + i * THREADS] = s2[tid + i * THREADS];
        float4* d3 = (float4*)b2s; const float4* s3 = (const float4*)b2;
        d3[tid] = s3[tid]; d3[tid + THREADS] = s3[tid + THREADS];
        if (tid < 32) b1s[tid] = b1[tid];
    }
    __syncthreads();

    const int r0 = blockIdx.x * ROWS_PER_CTA + tid;
    const int r1 = r0 + THREADS;
    const float* x0 = x + (size_t)r0 * IN_SZ;
    const float* x1 = x + (size_t)r1 * IN_SZ;
    const float* h0p = h + (size_t)r0 * HID_SZ;
    const float* h1p = h + (size_t)r1 * HID_SZ;

    // ---------------- GEMM1: z_pre[32] = combined[1024] . W1t (2 rows) ----------------
    u64 acc0[16], acc1[16];
    #pragma unroll
    for (int p = 0; p < 16; p++) { acc0[p] = 0ULL; acc1[p] = 0ULL; }

    gemm1_half(x0,  x1,  W1s, W1s,              acc0, acc1);   // k in [0,512): x
    gemm1_half(h0p, h1p, W1s, W1s + 512 * NZ,   acc0, acc1);   // k in [512,1024): h

    // z = tanh(z_pre + b1); dup-pack each z into both f32x2 lanes (per row)
    u64 z0[32], z1[32];
    #pragma unroll
    for (int p = 0; p < 16; p++) {
        float bA = b1s[2*p], bB = b1s[2*p + 1];
        float a, b;
        upk2(acc0[p], a, b);
        a = tanh_acc(a + bA); b = tanh_acc(b + bB);
        z0[2*p] = pk2(a, a);  z0[2*p + 1] = pk2(b, b);
        upk2(acc1[p], a, b);
        a = tanh_acc(a + bA); b = tanh_acc(b + bB);
        z1[2*p] = pk2(a, a);  z1[2*p + 1] = pk2(b, b);
    }

    // ---------------- GEMM2 + gating epilogue (2 rows share weight LDS) ----------------
    const float* c0p = c + (size_t)r0 * HID_SZ;
    const float* c1p = c + (size_t)r1 * HID_SZ;
    float* hn0 = out + (size_t)r0 * HID_SZ;
    float* hn1 = out + (size_t)r1 * HID_SZ;
    float* cn0 = out + (size_t)B_SZ * HID_SZ + (size_t)r0 * HID_SZ;
    float* cn1 = out + (size_t)B_SZ * HID_SZ + (size_t)r1 * HID_SZ;

    #pragma unroll 1
    for (int h0 = 0; h0 < HID_SZ; h0 += 4) {
        float pre0[4][4], pre1[4][4];
        #pragma unroll
        for (int g = 0; g < 4; g++) {
            ulonglong2 bb = *(const ulonglong2*)(b2s + g * HID_SZ + h0);
            u64 a0 = bb.x, a1 = bb.y;        // row0: pairs (h0,h0+1),(h0+2,h0+3)
            u64 e0 = bb.x, e1 = bb.y;        // row1
            const float* wg = W2s + g * (8 * HID_SZ) + h0;
            #pragma unroll
            for (int q = 0; q < 8; q++) {
                ulonglong2 w = *(const ulonglong2*)(wg + q * HID_SZ);
                u64 zq0 = z0[g*8 + q], zq1 = z1[g*8 + q];
                ffma2(a0, zq0, w.x);
                ffma2(a1, zq0, w.y);
                ffma2(e0, zq1, w.x);
                ffma2(e1, zq1, w.y);
            }
            upk2(a0, pre0[g][0], pre0[g][1]);
            upk2(a1, pre0[g][2], pre0[g][3]);
            upk2(e0, pre1[g][0], pre1[g][1]);
            upk2(e1, pre1[g][2], pre1[g][3]);
        }
        float4 cv0 = *(const float4*)(c0p + h0);
        float4 cv1 = *(const float4*)(c1p + h0);
        float ca0[4] = {cv0.x, cv0.y, cv0.z, cv0.w};
        float ca1[4] = {cv1.x, cv1.y, cv1.z, cv1.w};
        float hA[4], cA[4], hB[4], cB[4];
        #pragma unroll
        for (int j = 0; j < 4; j++) {
            float ig = sigm_fast(pre0[0][j]);
            float fg = sigm_fast(pre0[1][j]);
            float og = sigm_fast(pre0[2][j]);
            float gg = sigm_fast(pre0[3][j]);
            float cj = fmaf(fg, ca0[j], ig * gg);
            cA[j] = cj;
            hA[j] = og * tanh_fast(cj);

            ig = sigm_fast(pre1[0][j]);
            fg = sigm_fast(pre1[1][j]);
            og = sigm_fast(pre1[2][j]);
            gg = sigm_fast(pre1[3][j]);
            cj = fmaf(fg, ca1[j], ig * gg);
            cB[j] = cj;
            hB[j] = og * tanh_fast(cj);
        }
        *(float4*)(hn0 + h0) = make_float4(hA[0], hA[1], hA[2], hA[3]);
        *(float4*)(cn0 + h0) = make_float4(cA[0], cA[1], cA[2], cA[3]);
        *(float4*)(hn1 + h0) = make_float4(hB[0], hB[1], hB[2], hB[3]);
        *(float4*)(cn1 + h0) = make_float4(cB[0], cB[1], cB[2], cB[3]);
    }
}

extern "C" void kernel_launch(void* const* d_in, const int* in_sizes, int n_in,
                              void* d_out, int out_size) {
    const float* x  = (const float*)d_in[0];
    const float* h  = (const float*)d_in[1];
    const float* c  = (const float*)d_in[2];
    const float* W1 = (const float*)d_in[3];
    const float* b1 = (const float*)d_in[4];
    const float* W2 = (const float*)d_in[5];
    const float* b2 = (const float*)d_in[6];
    float* out = (float*)d_out;

    prep_kernel<<<192, 256>>>(W1, W2);   // 192*256 = 49152 = 32768 + 16384

    const size_t smem_bytes = (size_t)(32768 + 16384 + 2048 + 32) * sizeof(float); // 204,928 B
    cudaFuncSetAttribute(lstm_kernel, cudaFuncAttributeMaxDynamicSharedMemorySize,
                         (int)smem_bytes);
    lstm_kernel<<<NBLK, THREADS, smem_bytes>>>(x, h, c, b1, b2, out);
}